// round 5
// baseline (speedup 1.0000x reference)
#include <cuda_runtime.h>
#include <cstdint>

#define T_STEPS 2000
#define N_IN    8192
#define N_OUT   4096
#define M_PAD   2048

// 32 MB scratch for lif_input (allocation-free)
__device__ float g_lif[(size_t)M_PAD * N_OUT];

typedef unsigned long long ull;

// packed f32x2 fma: per-lane IEEE fma rounding, identical to scalar FFMA chains
__device__ __forceinline__ ull ffma2(ull a, ull b, ull c) {
    ull d;
    asm("fma.rn.f32x2 %0, %1, %2, %3;" : "=l"(d) : "l"(a), "l"(b), "l"(c));
    return d;
}

// ---------------------------------------------------------------------------
// FFMA2 SGEMM: C[M_PAD,N_OUT] = A[M,K] @ B[N,K]^T, fp32, ascending-k fma chain
// per output (bit-compatible with cuBLAS SIMT sgemm accumulation).
// Block tile 128(m) x 256(n), BK=8, 256 threads.
// Thread micro-tile: 16 m x 8 n held as 8x8 ULL regs (m-pairs packed in f32x2).
// ---------------------------------------------------------------------------
constexpr int BM = 128, BN = 256, BK = 8;

__global__ __launch_bounds__(256, 1)
void gemm_ffma2_kernel(const float* __restrict__ A,   // [M,K]
                       const float* __restrict__ B,   // [N,K]
                       float* __restrict__ C,         // [M_PAD,N_OUT]
                       int M, int K)
{
    __shared__ float As[BK][BM];          // 4 KB
    __shared__ float Bs2[BK][2 * BN];     // 16 KB (each B value duplicated)

    const int tid = threadIdx.x;
    const int bm  = blockIdx.x * BM;
    const int bn  = blockIdx.y * BN;

    // compute mapping: 8 m-groups (16 rows each) x 32 n-lanes (8 cols each)
    const int tr = (tid >> 5) * 16;       // warp-uniform -> a-loads broadcast
    const int ln = tid & 31;              // n col j: ln + 32*j

    // A loader: 128 rows x 8k, one float4 per thread (2 threads/row)
    const int aRow = tid >> 1;
    const int aCol = (tid & 1) * 4;
    const bool aValid = (bm + aRow) < M;
    const float* Aptr = A + (size_t)(bm + aRow) * K + aCol;

    // B loader: 256 rows x 8k, one row per thread
    const float* Bptr = B + (size_t)(bn + tid) * K;

    ull acc[8][8];
    #pragma unroll
    for (int i = 0; i < 8; i++)
        #pragma unroll
        for (int j = 0; j < 8; j++) acc[i][j] = 0ull;

    for (int k0 = 0; k0 < K; k0 += BK) {
        // ---- load A tile (transposed store, zero-pad rows >= M) ----
        float4 a4 = aValid ? *(const float4*)(Aptr + k0)
                           : make_float4(0.f, 0.f, 0.f, 0.f);
        As[aCol + 0][aRow] = a4.x;
        As[aCol + 1][aRow] = a4.y;
        As[aCol + 2][aRow] = a4.z;
        As[aCol + 3][aRow] = a4.w;

        // ---- load B tile, store duplicated pairs ----
        float4 b0 = *(const float4*)(Bptr + k0);
        float4 b1 = *(const float4*)(Bptr + k0 + 4);
        *(float2*)&Bs2[0][2 * tid] = make_float2(b0.x, b0.x);
        *(float2*)&Bs2[1][2 * tid] = make_float2(b0.y, b0.y);
        *(float2*)&Bs2[2][2 * tid] = make_float2(b0.z, b0.z);
        *(float2*)&Bs2[3][2 * tid] = make_float2(b0.w, b0.w);
        *(float2*)&Bs2[4][2 * tid] = make_float2(b1.x, b1.x);
        *(float2*)&Bs2[5][2 * tid] = make_float2(b1.y, b1.y);
        *(float2*)&Bs2[6][2 * tid] = make_float2(b1.z, b1.z);
        *(float2*)&Bs2[7][2 * tid] = make_float2(b1.w, b1.w);
        __syncthreads();

        #pragma unroll
        for (int k = 0; k < BK; k++) {
            ull a2[8], b2[8];
            #pragma unroll
            for (int i = 0; i < 8; i++)
                a2[i] = *(const ull*)&As[k][tr + 2 * i];      // (A[m], A[m+1])
            #pragma unroll
            for (int j = 0; j < 8; j++)
                b2[j] = *(const ull*)&Bs2[k][2 * (ln + 32 * j)];  // (b, b)
            #pragma unroll
            for (int i = 0; i < 8; i++)
                #pragma unroll
                for (int j = 0; j < 8; j++)
                    acc[i][j] = ffma2(a2[i], b2[j], acc[i][j]);
        }
        __syncthreads();
    }

    // ---- epilogue: lanes of acc[i][j] are rows (tr+2i, tr+2i+1), col ln+32j ----
    #pragma unroll
    for (int i = 0; i < 8; i++) {
        const int m0 = bm + tr + 2 * i;           // < 2048 always (C is padded)
        float* r0 = C + (size_t)m0 * N_OUT + bn + ln;
        float* r1 = r0 + N_OUT;
        #pragma unroll
        for (int j = 0; j < 8; j++) {
            float2 v = *(float2*)&acc[i][j];
            r0[32 * j] = v.x;
            r1[32 * j] = v.y;
        }
    }
}

// ---------------------------------------------------------------------------
// LIF scan — exact copy of the R1 kernel that passed with rel_err 0.0
// ---------------------------------------------------------------------------
__global__ __launch_bounds__(256)
void lif_scan_kernel(const float* __restrict__ lif,
                     float* __restrict__ out,
                     const float* __restrict__ v_th,
                     const float* __restrict__ v_rest,
                     const float* __restrict__ v_reset,
                     const float* __restrict__ t_ref,
                     const float* __restrict__ tau)
{
    const int n = blockIdx.x * blockDim.x + threadIdx.x;
    if (n >= N_OUT) return;

    const float DT   = 0.001f;
    const float th   = v_th[n];
    const float rest = v_rest[n];
    const float rst  = v_reset[n];
    const float trf  = t_ref[n];
    const float dt_tau = DT * tau[n];

    float v      = rest;
    float refrac = 0.0f;

    out[n] = 0.0f;

    for (int t = 1; t < T_STEPS; t++) {
        float inp = lif[(size_t)t * N_OUT + n];
        v = v - dt_tau * (v - rest);
        if (refrac == 0.0f) v += inp;
        refrac = (refrac > 0.0f) ? (refrac - DT) : 0.0f;
        float spike = (v - th >= 0.0f) ? 1.0f : 0.0f;
        if (spike > 0.0f) { refrac = trf; v = rst; }
        out[(size_t)t * N_OUT + n] = spike;
    }
}

// ---------------------------------------------------------------------------
extern "C" void kernel_launch(void* const* d_in, const int* in_sizes, int n_in,
                              void* d_out, int out_size)
{
    const float* x       = (const float*)d_in[0];  // [T, N_IN]
    const float* weight  = (const float*)d_in[1];  // [N_OUT, N_IN]
    const float* v_th    = (const float*)d_in[2];
    const float* v_rest  = (const float*)d_in[3];
    const float* v_reset = (const float*)d_in[4];
    const float* t_ref   = (const float*)d_in[5];
    const float* tau     = (const float*)d_in[6];
    float* out = (float*)d_out;

    float* lif_ptr = nullptr;
    cudaGetSymbolAddress((void**)&lif_ptr, g_lif);

    dim3 grid(M_PAD / BM, N_OUT / BN);   // (16, 16)
    gemm_ffma2_kernel<<<grid, 256>>>(x, weight, lif_ptr, T_STEPS, N_IN);

    lif_scan_kernel<<<N_OUT / 256, 256>>>(lif_ptr, out,
                                          v_th, v_rest, v_reset, t_ref, tau);
}

// round 6
// speedup vs baseline: 1.0587x; 1.0587x over previous
#include <cuda_runtime.h>

#define T_STEPS 2000
#define N_IN    8192
#define N_OUT   4096
#define M_PAD   2048

// 32 MB scratch for lif_input (allocation-free)
__device__ float g_lif[(size_t)M_PAD * N_OUT];
__device__ int   g_flags[16];

constexpr int BM = 128, BN = 128, BK = 8, TM = 8, TN = 8;
constexpr int N_BLK = N_OUT / BN;   // 32
constexpr int M_BLK = M_PAD / BM;   // 16
constexpr int SCAN_CTAS = 16;       // 16 * 256 = 4096 = N_OUT

__global__ void zero_flags_kernel() {
    if (threadIdx.x < M_BLK) g_flags[threadIdx.x] = 0;
}

__device__ __forceinline__ int ld_acquire_gpu(const int* p) {
    int v;
    asm volatile("ld.acquire.gpu.s32 %0, [%1];" : "=r"(v) : "l"(p) : "memory");
    return v;
}

// ---------------------------------------------------------------------------
// Fused kernel: blocks 0..15 run the LIF scan (polling per-m-block flags),
// blocks 16..527 run the R1 SGEMM (math/order IDENTICAL to the passing R1
// kernel: ascending-k fp32 fma chain per output).
// ---------------------------------------------------------------------------
__global__ __launch_bounds__(256, 2)
void fused_gemm_scan_kernel(const float* __restrict__ A,   // x [M, K]
                            const float* __restrict__ B,   // w [N, K]
                            const float* __restrict__ v_th,
                            const float* __restrict__ v_rest,
                            const float* __restrict__ v_reset,
                            const float* __restrict__ t_ref,
                            const float* __restrict__ tau,
                            float* __restrict__ out,
                            int M, int N, int K)
{
    __shared__ float As[BK][BM];
    __shared__ float Bs[BK][BN];

    const int bid = blockIdx.x;
    const int tid = threadIdx.x;

    if (bid >= SCAN_CTAS) {
        // =================== GEMM branch (bit-exact R1) ===================
        const int g  = bid - SCAN_CTAS;
        const int mb = g >> 5;              // m-block index 0..15 (dispatched first)
        const int bm = mb * BM;
        const int bn = (g & 31) * BN;
        float* C = g_lif;

        const int loadRow = tid >> 1;
        const int loadCol = (tid & 1) * 4;
        const int tr = (tid >> 4) * TM;
        const int tc = (tid & 15) * TN;

        float acc[TM][TN];
        #pragma unroll
        for (int i = 0; i < TM; i++)
            #pragma unroll
            for (int j = 0; j < TN; j++)
                acc[i][j] = 0.0f;

        const bool aValid = (bm + loadRow) < M;
        const float* Aptr = A + (size_t)(bm + loadRow) * K + loadCol;
        const float* Bptr = B + (size_t)(bn + loadRow) * K + loadCol;

        for (int k0 = 0; k0 < K; k0 += BK) {
            float4 a4 = aValid ? *(const float4*)(Aptr + k0)
                               : make_float4(0.f, 0.f, 0.f, 0.f);
            float4 b4 = *(const float4*)(Bptr + k0);

            As[loadCol + 0][loadRow] = a4.x;
            As[loadCol + 1][loadRow] = a4.y;
            As[loadCol + 2][loadRow] = a4.z;
            As[loadCol + 3][loadRow] = a4.w;
            Bs[loadCol + 0][loadRow] = b4.x;
            Bs[loadCol + 1][loadRow] = b4.y;
            Bs[loadCol + 2][loadRow] = b4.z;
            Bs[loadCol + 3][loadRow] = b4.w;
            __syncthreads();

            #pragma unroll
            for (int k = 0; k < BK; k++) {
                float ar[TM], br[TN];
                #pragma unroll
                for (int i = 0; i < TM; i++) ar[i] = As[k][tr + i];
                #pragma unroll
                for (int j = 0; j < TN; j++) br[j] = Bs[k][tc + j];
                #pragma unroll
                for (int i = 0; i < TM; i++)
                    #pragma unroll
                    for (int j = 0; j < TN; j++)
                        acc[i][j] += ar[i] * br[j];
            }
            __syncthreads();
        }

        #pragma unroll
        for (int i = 0; i < TM; i++) {
            int gm = bm + tr + i;
            if (gm < M) {
                float* Crow = C + (size_t)gm * N + bn + tc;
                #pragma unroll
                for (int j = 0; j < TN; j += 4) {
                    float4 v = make_float4(acc[i][j], acc[i][j+1],
                                           acc[i][j+2], acc[i][j+3]);
                    *(float4*)(Crow + j) = v;
                }
            }
        }

        // signal: this (mb, nb) tile is globally visible
        __threadfence();
        __syncthreads();
        if (tid == 0) atomicAdd(&g_flags[mb], 1);

    } else {
        // =================== LIF scan branch ===================
        const int n = bid * 256 + tid;      // 0..4095

        const float DT   = 0.001f;
        const float th   = v_th[n];
        const float rest = v_rest[n];
        const float rst  = v_reset[n];
        const float trf  = t_ref[n];
        const float dt_tau = DT * tau[n];

        float v = rest;
        float refrac = 0.0f;
        out[n] = 0.0f;                      // s[0] = 0

        const float* lif = g_lif;

        for (int b = 0; b < M_BLK; b++) {
            const int t0 = (b == 0) ? 1 : b * BM;
            const int t1 = (b + 1) * BM < T_STEPS ? (b + 1) * BM : T_STEPS;
            if (t0 >= t1) break;

            // wait until all 32 n-tiles of m-block b are complete
            if (tid == 0) {
                while (ld_acquire_gpu(&g_flags[b]) < N_BLK) __nanosleep(200);
            }
            __syncthreads();

            int t = t0;
            while (t < t1) {
                int nb = t1 - t; if (nb > 8) nb = 8;
                float buf[8];
                #pragma unroll
                for (int j = 0; j < 8; j++)
                    if (j < nb) buf[j] = lif[(size_t)(t + j) * N_OUT + n];
                #pragma unroll
                for (int j = 0; j < 8; j++) {
                    if (j < nb) {
                        float inp = buf[j];
                        v = v - dt_tau * (v - rest);
                        if (refrac == 0.0f) v += inp;
                        refrac = (refrac > 0.0f) ? (refrac - DT) : 0.0f;
                        float spike = (v - th >= 0.0f) ? 1.0f : 0.0f;
                        if (spike > 0.0f) { refrac = trf; v = rst; }
                        out[(size_t)(t + j) * N_OUT + n] = spike;
                    }
                }
                t += nb;
            }
        }
    }
}

// ---------------------------------------------------------------------------
extern "C" void kernel_launch(void* const* d_in, const int* in_sizes, int n_in,
                              void* d_out, int out_size)
{
    const float* x       = (const float*)d_in[0];  // [T, N_IN]
    const float* weight  = (const float*)d_in[1];  // [N_OUT, N_IN]
    const float* v_th    = (const float*)d_in[2];
    const float* v_rest  = (const float*)d_in[3];
    const float* v_reset = (const float*)d_in[4];
    const float* t_ref   = (const float*)d_in[5];
    const float* tau     = (const float*)d_in[6];
    float* out = (float*)d_out;

    zero_flags_kernel<<<1, 32>>>();

    // 16 scan CTAs first (resident from wave 1), then 512 GEMM CTAs
    const int grid = SCAN_CTAS + M_BLK * N_BLK;   // 528
    fused_gemm_scan_kernel<<<grid, 256>>>(x, weight,
                                          v_th, v_rest, v_reset, t_ref, tau,
                                          out, T_STEPS, N_OUT, N_IN);
}

// round 7
// speedup vs baseline: 1.0834x; 1.0234x over previous
#include <cuda_runtime.h>

#define T_STEPS 2000
#define N_IN    8192
#define N_OUT   4096

// 32 MB scratch for lif_input = x @ W^T  (allocation-free: __device__ global)
__device__ float g_lif[(size_t)T_STEPS * N_OUT];

// ---------------------------------------------------------------------------
// Phase 1: fp32 GEMM — byte-for-byte the R1 kernel that runs at 36.6 TF/s
// (100% of the fp32 FFMA pipe) and produces the bit-exact ascending-k chain.
// ---------------------------------------------------------------------------
constexpr int BM = 128, BN = 128, BK = 8, TM = 8, TN = 8;

__global__ __launch_bounds__(256, 2)
void gemm_nt_kernel(const float* __restrict__ A,   // [M,K]
                    const float* __restrict__ B,   // [N,K]
                    float* __restrict__ C,         // [M,N]
                    int M, int N, int K)
{
    __shared__ float As[BK][BM];
    __shared__ float Bs[BK][BN];

    const int tid = threadIdx.x;
    const int bm  = blockIdx.y * BM;
    const int bn  = blockIdx.x * BN;

    const int loadRow = tid >> 1;         // 0..127
    const int loadCol = (tid & 1) * 4;    // 0 or 4

    const int tr = (tid >> 4) * TM;       // 0..120
    const int tc = (tid & 15) * TN;       // 0..120

    float acc[TM][TN];
    #pragma unroll
    for (int i = 0; i < TM; i++)
        #pragma unroll
        for (int j = 0; j < TN; j++)
            acc[i][j] = 0.0f;

    const bool aValid = (bm + loadRow) < M;
    const float* Aptr = A + (size_t)(bm + loadRow) * K + loadCol;
    const float* Bptr = B + (size_t)(bn + loadRow) * K + loadCol;

    for (int k0 = 0; k0 < K; k0 += BK) {
        float4 a4 = aValid ? *(const float4*)(Aptr + k0)
                           : make_float4(0.f, 0.f, 0.f, 0.f);
        float4 b4 = *(const float4*)(Bptr + k0);

        As[loadCol + 0][loadRow] = a4.x;
        As[loadCol + 1][loadRow] = a4.y;
        As[loadCol + 2][loadRow] = a4.z;
        As[loadCol + 3][loadRow] = a4.w;
        Bs[loadCol + 0][loadRow] = b4.x;
        Bs[loadCol + 1][loadRow] = b4.y;
        Bs[loadCol + 2][loadRow] = b4.z;
        Bs[loadCol + 3][loadRow] = b4.w;
        __syncthreads();

        #pragma unroll
        for (int k = 0; k < BK; k++) {
            float ar[TM], br[TN];
            #pragma unroll
            for (int i = 0; i < TM; i++) ar[i] = As[k][tr + i];
            #pragma unroll
            for (int j = 0; j < TN; j++) br[j] = Bs[k][tc + j];
            #pragma unroll
            for (int i = 0; i < TM; i++)
                #pragma unroll
                for (int j = 0; j < TN; j++)
                    acc[i][j] += ar[i] * br[j];
        }
        __syncthreads();
    }

    #pragma unroll
    for (int i = 0; i < TM; i++) {
        int gm = bm + tr + i;
        if (gm < M) {
            float* Crow = C + (size_t)gm * N + bn + tc;
            #pragma unroll
            for (int j = 0; j < TN; j += 4) {
                float4 v = make_float4(acc[i][j], acc[i][j+1],
                                       acc[i][j+2], acc[i][j+3]);
                *(float4*)(Crow + j) = v;
            }
        }
    }
}

// ---------------------------------------------------------------------------
// Phase 2: LIF scan — identical per-step arithmetic to the rel_err-0.0 version.
// Changes (scheduling only): 128 CTAs x 32 threads -> 128 SMs instead of 16,
// and 8-deep register prefetch -> MLP 8 instead of 1.
// ---------------------------------------------------------------------------
constexpr int PF = 8;

__global__ __launch_bounds__(32)
void lif_scan_kernel(const float* __restrict__ lif,
                     float* __restrict__ out,
                     const float* __restrict__ v_th,
                     const float* __restrict__ v_rest,
                     const float* __restrict__ v_reset,
                     const float* __restrict__ t_ref,
                     const float* __restrict__ tau)
{
    const int n = blockIdx.x * 32 + threadIdx.x;   // 128 * 32 = 4096 = N_OUT

    const float DT   = 0.001f;
    const float th   = v_th[n];
    const float rest = v_rest[n];
    const float rst  = v_reset[n];
    const float trf  = t_ref[n];
    const float dt_tau = DT * tau[n];

    float v      = rest;   // v[0] = v_rest
    float refrac = 0.0f;

    out[n] = 0.0f;         // s[0] = 0

    // prime prefetch buffer with t = 1..8
    float buf[PF];
    #pragma unroll
    for (int j = 0; j < PF; j++)
        buf[j] = lif[(size_t)(1 + j) * N_OUT + n];

    for (int tb = 1; tb < T_STEPS; tb += PF) {
        float cur[PF];
        #pragma unroll
        for (int j = 0; j < PF; j++) cur[j] = buf[j];

        // issue next batch of loads (MLP = 8) before consuming current batch
        #pragma unroll
        for (int j = 0; j < PF; j++) {
            int tn = tb + PF + j;
            buf[j] = (tn < T_STEPS) ? lif[(size_t)tn * N_OUT + n] : 0.0f;
        }

        #pragma unroll
        for (int j = 0; j < PF; j++) {
            int t = tb + j;
            if (t < T_STEPS) {
                float inp = cur[j];
                // leak toward v_rest
                v = v - dt_tau * (v - rest);
                // integrate only when not refractory
                if (refrac == 0.0f) v += inp;
                // count down refractory period
                refrac = (refrac > 0.0f) ? (refrac - DT) : 0.0f;
                // heavyside spike
                float spike = (v - th >= 0.0f) ? 1.0f : 0.0f;
                // reset
                if (spike > 0.0f) { refrac = trf; v = rst; }
                out[(size_t)t * N_OUT + n] = spike;
            }
        }
    }
}

// ---------------------------------------------------------------------------
extern "C" void kernel_launch(void* const* d_in, const int* in_sizes, int n_in,
                              void* d_out, int out_size)
{
    const float* x       = (const float*)d_in[0];  // [T, N_IN]
    const float* weight  = (const float*)d_in[1];  // [N_OUT, N_IN]
    const float* v_th    = (const float*)d_in[2];
    const float* v_rest  = (const float*)d_in[3];
    const float* v_reset = (const float*)d_in[4];
    const float* t_ref   = (const float*)d_in[5];
    const float* tau     = (const float*)d_in[6];
    float* out = (float*)d_out;                    // [T, N_OUT]

    float* lif_ptr = nullptr;
    cudaGetSymbolAddress((void**)&lif_ptr, g_lif);

    // GEMM: M=2000, N=4096, K=8192 (unchanged — fp32 pipe-saturated)
    dim3 grid(N_OUT / BN, (T_STEPS + BM - 1) / BM);
    gemm_nt_kernel<<<grid, 256>>>(x, weight, lif_ptr, T_STEPS, N_OUT, N_IN);

    // Scan: 128 CTAs x 1 warp -> 128 SMs, MLP 8
    lif_scan_kernel<<<128, 32>>>(lif_ptr, out,
                                 v_th, v_rest, v_reset, t_ref, tau);
}

// round 8
// speedup vs baseline: 1.1016x; 1.0168x over previous
#include <cuda_runtime.h>

#define T_STEPS 2000
#define N_IN    8192
#define N_OUT   4096

// 32 MB scratch for lif_input = x @ W^T  (allocation-free: __device__ global)
__device__ float g_lif[(size_t)T_STEPS * N_OUT];

// ---------------------------------------------------------------------------
// Phase 1: fp32 GEMM — byte-for-byte the R1 kernel (36 TF/s, fp32 pipe
// ceiling, bit-exact ascending-k fma chain per output).
// ---------------------------------------------------------------------------
constexpr int BM = 128, BN = 128, BK = 8, TM = 8, TN = 8;

__global__ __launch_bounds__(256, 2)
void gemm_nt_kernel(const float* __restrict__ A,   // [M,K]
                    const float* __restrict__ B,   // [N,K]
                    float* __restrict__ C,         // [M,N]
                    int M, int N, int K)
{
    __shared__ float As[BK][BM];
    __shared__ float Bs[BK][BN];

    const int tid = threadIdx.x;
    const int bm  = blockIdx.y * BM;
    const int bn  = blockIdx.x * BN;

    const int loadRow = tid >> 1;
    const int loadCol = (tid & 1) * 4;

    const int tr = (tid >> 4) * TM;
    const int tc = (tid & 15) * TN;

    float acc[TM][TN];
    #pragma unroll
    for (int i = 0; i < TM; i++)
        #pragma unroll
        for (int j = 0; j < TN; j++)
            acc[i][j] = 0.0f;

    const bool aValid = (bm + loadRow) < M;
    const float* Aptr = A + (size_t)(bm + loadRow) * K + loadCol;
    const float* Bptr = B + (size_t)(bn + loadRow) * K + loadCol;

    for (int k0 = 0; k0 < K; k0 += BK) {
        float4 a4 = aValid ? *(const float4*)(Aptr + k0)
                           : make_float4(0.f, 0.f, 0.f, 0.f);
        float4 b4 = *(const float4*)(Bptr + k0);

        As[loadCol + 0][loadRow] = a4.x;
        As[loadCol + 1][loadRow] = a4.y;
        As[loadCol + 2][loadRow] = a4.z;
        As[loadCol + 3][loadRow] = a4.w;
        Bs[loadCol + 0][loadRow] = b4.x;
        Bs[loadCol + 1][loadRow] = b4.y;
        Bs[loadCol + 2][loadRow] = b4.z;
        Bs[loadCol + 3][loadRow] = b4.w;
        __syncthreads();

        #pragma unroll
        for (int k = 0; k < BK; k++) {
            float ar[TM], br[TN];
            #pragma unroll
            for (int i = 0; i < TM; i++) ar[i] = As[k][tr + i];
            #pragma unroll
            for (int j = 0; j < TN; j++) br[j] = Bs[k][tc + j];
            #pragma unroll
            for (int i = 0; i < TM; i++)
                #pragma unroll
                for (int j = 0; j < TN; j++)
                    acc[i][j] += ar[i] * br[j];
        }
        __syncthreads();
    }

    #pragma unroll
    for (int i = 0; i < TM; i++) {
        int gm = bm + tr + i;
        if (gm < M) {
            float* Crow = C + (size_t)gm * N + bn + tc;
            #pragma unroll
            for (int j = 0; j < TN; j += 4) {
                float4 v = make_float4(acc[i][j], acc[i][j+1],
                                       acc[i][j+2], acc[i][j+3]);
                *(float4*)(Crow + j) = v;
            }
        }
    }
}

// ---------------------------------------------------------------------------
// Phase 2: LIF scan — branch-free select form. Values per step are identical
// to the rel_err-0.0 version; only predication style / loop structure change.
// ---------------------------------------------------------------------------
constexpr int PF = 16;          // 1999 = 16 (prime) + 123*16 + 15 (tail)
constexpr int NBATCH = 123;
constexpr int TAIL = 15;

__device__ __forceinline__ float lif_step(float inp, float& v, float& refrac,
                                          float dt_tau, float rest, float th,
                                          float rst, float trf)
{
    const float DT = 0.001f;
    // leak toward v_rest  (same expression as R1 -> same FFMA contraction)
    float v1 = v - dt_tau * (v - rest);
    // integrate only when not refractory (select form, same value)
    float va = v1 + inp;
    v1 = (refrac == 0.0f) ? va : v1;
    // count down refractory period
    float rf = refrac - DT;
    rf = (refrac > 0.0f) ? rf : 0.0f;
    // heavyside spike
    float spike = (v1 - th >= 0.0f) ? 1.0f : 0.0f;
    // reset
    bool sb = (spike > 0.0f);
    refrac = sb ? trf : rf;
    v = sb ? rst : v1;
    return spike;
}

__global__ __launch_bounds__(32)
void lif_scan_kernel(const float* __restrict__ lif,
                     float* __restrict__ out,
                     const float* __restrict__ v_th,
                     const float* __restrict__ v_rest,
                     const float* __restrict__ v_reset,
                     const float* __restrict__ t_ref,
                     const float* __restrict__ tau)
{
    const int n = blockIdx.x * 32 + threadIdx.x;   // 128*32 = 4096

    const float th   = v_th[n];
    const float rest = v_rest[n];
    const float rst  = v_reset[n];
    const float trf  = t_ref[n];
    const float dt_tau = 0.001f * tau[n];

    float v = rest;        // v[0] = v_rest
    float refrac = 0.0f;

    out[n] = 0.0f;         // s[0] = 0

    const float* p = lif + (size_t)1 * N_OUT + n;  // input for t=1
    float*       q = out + (size_t)1 * N_OUT + n;  // spike  for t=1

    // prime: t = 1..16
    float buf[PF];
    #pragma unroll
    for (int j = 0; j < PF; j++) buf[j] = p[(size_t)j * N_OUT];
    p += (size_t)PF * N_OUT;

    // 123 full batches: consume 16, prefetch 16 (last prefetch covers t<=1984)
    for (int b = 0; b < NBATCH; b++) {
        float cur[PF];
        #pragma unroll
        for (int j = 0; j < PF; j++) cur[j] = buf[j];
        #pragma unroll
        for (int j = 0; j < PF; j++) buf[j] = p[(size_t)j * N_OUT];
        p += (size_t)PF * N_OUT;
        #pragma unroll
        for (int j = 0; j < PF; j++) {
            q[(size_t)j * N_OUT] =
                lif_step(cur[j], v, refrac, dt_tau, rest, th, rst, trf);
        }
        q += (size_t)PF * N_OUT;
    }

    // buffered batch: t = 1969..1984
    {
        float tail[TAIL];   // prefetch the final 15 inputs (t = 1985..1999)
        #pragma unroll
        for (int j = 0; j < TAIL; j++) tail[j] = p[(size_t)j * N_OUT];
        #pragma unroll
        for (int j = 0; j < PF; j++) {
            q[(size_t)j * N_OUT] =
                lif_step(buf[j], v, refrac, dt_tau, rest, th, rst, trf);
        }
        q += (size_t)PF * N_OUT;
        // tail: t = 1985..1999
        #pragma unroll
        for (int j = 0; j < TAIL; j++) {
            q[(size_t)j * N_OUT] =
                lif_step(tail[j], v, refrac, dt_tau, rest, th, rst, trf);
        }
    }
}

// ---------------------------------------------------------------------------
extern "C" void kernel_launch(void* const* d_in, const int* in_sizes, int n_in,
                              void* d_out, int out_size)
{
    const float* x       = (const float*)d_in[0];  // [T, N_IN]
    const float* weight  = (const float*)d_in[1];  // [N_OUT, N_IN]
    const float* v_th    = (const float*)d_in[2];
    const float* v_rest  = (const float*)d_in[3];
    const float* v_reset = (const float*)d_in[4];
    const float* t_ref   = (const float*)d_in[5];
    const float* tau     = (const float*)d_in[6];
    float* out = (float*)d_out;                    // [T, N_OUT]

    float* lif_ptr = nullptr;
    cudaGetSymbolAddress((void**)&lif_ptr, g_lif);

    // GEMM: M=2000, N=4096, K=8192 (unchanged)
    dim3 grid(N_OUT / BN, (T_STEPS + BM - 1) / BM);
    gemm_nt_kernel<<<grid, 256>>>(x, weight, lif_ptr, T_STEPS, N_OUT, N_IN);

    // Scan: 128 CTAs x 1 warp
    lif_scan_kernel<<<128, 32>>>(lif_ptr, out,
                                 v_th, v_rest, v_reset, t_ref, tau);
}